// round 6
// baseline (speedup 1.0000x reference)
#include <cuda_runtime.h>

#define NTOT 40960
#define ETOT 81920
#define GTOT 1024
#define NC   512

typedef unsigned long long u64;

__device__ __forceinline__ u64 pack2(float x) {
    u64 r; asm("mov.b64 %0, {%1, %1};" : "=l"(r) : "f"(x)); return r;
}
__device__ __forceinline__ void fma2(u64& d, u64 a, u64 b) {
    asm("fma.rn.f32x2 %0, %1, %2, %0;" : "+l"(d) : "l"(a), "l"(b));
}
__device__ __forceinline__ float2 unpack2(u64 v) {
    float lo, hi;
    asm("mov.b64 {%0, %1}, %2;" : "=f"(lo), "=f"(hi) : "l"(v));
    return make_float2(lo, hi);
}

// ---------------- scratch ---------------------------------------------------
__device__ __align__(16) float g_x[NTOT * 64];
__device__ __align__(16) float g_h1[NC * 1024];
__device__ __align__(16) float g_h2[NC * 256];
__device__ __align__(16) float g_W[NC * 2048];
__device__ __align__(16) float g_dense[GTOT * 1280];
__device__ __align__(16) float g_f1[GTOT * 256];
__device__ __align__(16) float g_f2[GTOT * 128];
__device__ __align__(16) float g_bias1[256];
__device__ int g_combo[ETOT];
__device__ int g_hist[NC];
__device__ int g_off[NC];
__device__ int g_cursor[NC];
__device__ int g_sorted[ETOT];

// ---------------- zero fill -------------------------------------------------
__global__ void zero2_k(float4* a, int na, float4* b, int nb) {
    const int stride = gridDim.x * blockDim.x;
    const float4 z = make_float4(0.f, 0.f, 0.f, 0.f);
    for (int i = blockIdx.x * blockDim.x + threadIdx.x; i < na; i += stride) a[i] = z;
    for (int i = blockIdx.x * blockDim.x + threadIdx.x; i < nb; i += stride) b[i] = z;
}

// ---------------- prep ------------------------------------------------------
__global__ void encode_x_k(const int* __restrict__ nf,
                           const float* __restrict__ atom) {
    __shared__ int s_nf[4][9];
    const int tid = threadIdx.x;
    if (tid < 36) {
        int nl = tid / 9, c = tid % 9;
        s_nf[nl][c] = nf[(blockIdx.x * 4 + nl) * 9 + c];
    }
    __syncthreads();
    const int nl = tid >> 6;
    const int d  = tid & 63;
    const int n  = blockIdx.x * 4 + nl;
    float acc = 0.f;
#pragma unroll
    for (int c = 0; c < 9; c++)
        acc += atom[(c * 128 + s_nf[nl][c]) * 64 + d];
    g_x[n * 64 + d] = acc;
}

__global__ void combo_k(const int* __restrict__ ef) {
    int e = blockIdx.x * 256 + threadIdx.x;
    int c = ef[e * 3] * 64 + ef[e * 3 + 1] * 8 + ef[e * 3 + 2];
    g_combo[e] = c;
    atomicAdd(&g_hist[c], 1);
}

__global__ void scan_k() {
    __shared__ int wsum[16];
    int t = threadIdx.x;
    int v = g_hist[t];
    int lane = t & 31, w = t >> 5;
    int s = v;
#pragma unroll
    for (int d = 1; d < 32; d <<= 1) {
        int u = __shfl_up_sync(0xffffffffu, s, d);
        if (lane >= d) s += u;
    }
    if (lane == 31) wsum[w] = s;
    __syncthreads();
    if (t < 16) {
        int x = wsum[t];
#pragma unroll
        for (int d = 1; d < 16; d <<= 1) {
            int u = __shfl_up_sync(0xffffu, x, d);
            if (t >= d) x += u;
        }
        wsum[t] = x;
    }
    __syncthreads();
    int off = (w > 0 ? wsum[w - 1] : 0) + s - v;
    g_off[t] = off;
    g_cursor[t] = off;
}

__global__ void scatter_k() {
    int e = blockIdx.x * 256 + threadIdx.x;
    int c = g_combo[e];
    int p = atomicAdd(&g_cursor[c], 1);
    g_sorted[p] = e;
}

// ---------------- E1: h1 = relu(eu @ gW1) -----------------------------------
__global__ void gemmE1_k(const float* __restrict__ bond,
                         const float* __restrict__ gW1) {
    __shared__ float bnd[384];
    __shared__ float As[16][64];
    __shared__ float Bs[16][64];
    const int tid = threadIdx.x;
    for (int i = tid; i < 384; i += 256) bnd[i] = bond[i];
    __syncthreads();
    for (int idx = tid; idx < 1024; idx += 256) {
        int r = idx >> 4, j = idx & 15;
        int c = blockIdx.y * 64 + r;
        As[j][r] = bnd[(c >> 6) * 16 + j]
                 + bnd[128 + ((c >> 3) & 7) * 16 + j]
                 + bnd[256 + (c & 7) * 16 + j];
    }
    {
        int bk = tid >> 4, bn = (tid & 15) << 2;
        *(float4*)&Bs[bk][bn] = *(const float4*)(gW1 + (size_t)bk * 1024 + blockIdx.x * 64 + bn);
    }
    __syncthreads();
    const int trow = tid >> 4, tcol = tid & 15;
    float acc[4][4] = {};
#pragma unroll
    for (int k = 0; k < 16; k++) {
        float4 a = *(const float4*)&As[k][trow << 2];
        float4 b = *(const float4*)&Bs[k][tcol << 2];
        float ar[4] = {a.x, a.y, a.z, a.w};
        float br[4] = {b.x, b.y, b.z, b.w};
#pragma unroll
        for (int i = 0; i < 4; i++)
#pragma unroll
            for (int j = 0; j < 4; j++)
                acc[i][j] += ar[i] * br[j];
    }
    int row0 = blockIdx.y * 64 + (trow << 2);
    int col0 = blockIdx.x * 64 + (tcol << 2);
#pragma unroll
    for (int i = 0; i < 4; i++) {
        float4 o;
        o.x = fmaxf(acc[i][0], 0.f); o.y = fmaxf(acc[i][1], 0.f);
        o.z = fmaxf(acc[i][2], 0.f); o.w = fmaxf(acc[i][3], 0.f);
        *(float4*)(g_h1 + (size_t)(row0 + i) * 1024 + col0) = o;
    }
}

// ---------------- gemm3: packed-f32x2, 64x128 tile, double-buffered ---------
// grid (N/128, M/64, splits), KC per split (KC % 16 == 0).
// C = A[M,lda] @ B[K,N]; epilogue: plain store (STORE_C) or atomicAdd.
template <bool RELU_A, bool STORE_C>
__global__ void __launch_bounds__(256) gemm3_k(
        const float* __restrict__ A, const float* __restrict__ B,
        float* __restrict__ C, int N, int lda, int ldb, int KC) {
    __shared__ float As[2][16][68];
    __shared__ float Bs[2][16][128];
    const int tid  = threadIdx.x;
    const int trow = (tid >> 4) << 2;      // 0..60
    const int tcol = (tid & 15) << 3;      // 0..120
    const int lr = tid >> 2, lk = (tid & 3) << 2;
    const int bk = tid >> 4, bn = (tid & 15) << 3;
    const float* Ag = A + (size_t)(blockIdx.y * 64 + lr) * lda + blockIdx.z * KC + lk;
    const float* Bg = B + (size_t)((size_t)blockIdx.z * KC + bk) * ldb + blockIdx.x * 128 + bn;
    const int ntiles = KC >> 4;

    u64 acc[4][4];
#pragma unroll
    for (int i = 0; i < 4; i++)
#pragma unroll
        for (int j = 0; j < 4; j++) acc[i][j] = 0ull;

    float4 av = *(const float4*)Ag;
    float4 bv0 = *(const float4*)Bg;
    float4 bv1 = *(const float4*)(Bg + 4);
    if (RELU_A) {
        av.x = fmaxf(av.x, 0.f); av.y = fmaxf(av.y, 0.f);
        av.z = fmaxf(av.z, 0.f); av.w = fmaxf(av.w, 0.f);
    }
    As[0][lk + 0][lr] = av.x; As[0][lk + 1][lr] = av.y;
    As[0][lk + 2][lr] = av.z; As[0][lk + 3][lr] = av.w;
    *(float4*)&Bs[0][bk][bn] = bv0;
    *(float4*)&Bs[0][bk][bn + 4] = bv1;
    __syncthreads();

    for (int t = 0; t < ntiles; t++) {
        const int cur = t & 1;
        if (t + 1 < ntiles) {
            av  = *(const float4*)(Ag + (t + 1) * 16);
            bv0 = *(const float4*)(Bg + (size_t)(t + 1) * 16 * ldb);
            bv1 = *(const float4*)(Bg + (size_t)(t + 1) * 16 * ldb + 4);
        }
#pragma unroll
        for (int k = 0; k < 16; k++) {
            float4 a4 = *(const float4*)&As[cur][k][trow];
            ulonglong2 q0 = *(const ulonglong2*)&Bs[cur][k][tcol];
            ulonglong2 q1 = *(const ulonglong2*)&Bs[cur][k][tcol + 4];
            u64 ap;
            ap = pack2(a4.x);
            fma2(acc[0][0], ap, q0.x); fma2(acc[0][1], ap, q0.y);
            fma2(acc[0][2], ap, q1.x); fma2(acc[0][3], ap, q1.y);
            ap = pack2(a4.y);
            fma2(acc[1][0], ap, q0.x); fma2(acc[1][1], ap, q0.y);
            fma2(acc[1][2], ap, q1.x); fma2(acc[1][3], ap, q1.y);
            ap = pack2(a4.z);
            fma2(acc[2][0], ap, q0.x); fma2(acc[2][1], ap, q0.y);
            fma2(acc[2][2], ap, q1.x); fma2(acc[2][3], ap, q1.y);
            ap = pack2(a4.w);
            fma2(acc[3][0], ap, q0.x); fma2(acc[3][1], ap, q0.y);
            fma2(acc[3][2], ap, q1.x); fma2(acc[3][3], ap, q1.y);
        }
        if (t + 1 < ntiles) {
            const int nxt = cur ^ 1;
            if (RELU_A) {
                av.x = fmaxf(av.x, 0.f); av.y = fmaxf(av.y, 0.f);
                av.z = fmaxf(av.z, 0.f); av.w = fmaxf(av.w, 0.f);
            }
            As[nxt][lk + 0][lr] = av.x; As[nxt][lk + 1][lr] = av.y;
            As[nxt][lk + 2][lr] = av.z; As[nxt][lk + 3][lr] = av.w;
            *(float4*)&Bs[nxt][bk][bn] = bv0;
            *(float4*)&Bs[nxt][bk][bn + 4] = bv1;
        }
        __syncthreads();
    }

    const int row0 = blockIdx.y * 64 + trow;
    const int col0 = blockIdx.x * 128 + tcol;
#pragma unroll
    for (int i = 0; i < 4; i++) {
        float2 p0 = unpack2(acc[i][0]), p1 = unpack2(acc[i][1]);
        float2 p2 = unpack2(acc[i][2]), p3 = unpack2(acc[i][3]);
        float* cp = C + (size_t)(row0 + i) * N + col0;
        if (STORE_C) {
            *(float4*)cp       = make_float4(p0.x, p0.y, p1.x, p1.y);
            *(float4*)(cp + 4) = make_float4(p2.x, p2.y, p3.x, p3.y);
        } else {
            atomicAdd(cp + 0, p0.x); atomicAdd(cp + 1, p0.y);
            atomicAdd(cp + 2, p1.x); atomicAdd(cp + 3, p1.y);
            atomicAdd(cp + 4, p2.x); atomicAdd(cp + 5, p2.y);
            atomicAdd(cp + 6, p3.x); atomicAdd(cp + 7, p3.y);
        }
    }
}

// ---------------- bias1 = (conv_bias tiled over 1280) @ mW1 -----------------
__global__ void biasR1_k(const float* __restrict__ mW1,
                         const float* __restrict__ cb) {
    const int c = threadIdx.x;
    const int k0 = blockIdx.x * 8;
    float acc = 0.f;
#pragma unroll
    for (int k = k0; k < k0 + 8; k++)
        acc += cb[k & 31] * mW1[(size_t)k * 256 + c];
    atomicAdd(&g_bias1[c], acc);
}

__global__ void f1init_k(const float* __restrict__ mb1) {
    int i = blockIdx.x * 256 + threadIdx.x;
    int c = i & 255;
    g_f1[i] = g_bias1[c] + mb1[c];
}

// ---------------- message passing -------------------------------------------
__global__ void msg_root_k(const float* __restrict__ root) {
    __shared__ float Ws[2048];
    __shared__ float Xs[128 * 68];
    const int tid = threadIdx.x;
    const int n0 = blockIdx.x * 128;
    for (int i = tid; i < 512; i += 256)
        ((float4*)Ws)[i] = ((const float4*)root)[i];
    for (int idx = tid; idx < 128 * 16; idx += 256) {
        int j = idx >> 4, kq = idx & 15;
        ((float4*)(Xs + j * 68))[kq] = ((const float4*)(g_x + (size_t)(n0 + j) * 64))[kq];
    }
    __syncthreads();
    const int e0 = (tid >> 3) << 2;
    const int c0 = (tid & 7) << 2;
    float acc[4][4] = {};
#pragma unroll 4
    for (int kk = 0; kk < 64; kk += 4) {
        float4 w0 = *(const float4*)&Ws[(kk + 0) * 32 + c0];
        float4 w1 = *(const float4*)&Ws[(kk + 1) * 32 + c0];
        float4 w2 = *(const float4*)&Ws[(kk + 2) * 32 + c0];
        float4 w3 = *(const float4*)&Ws[(kk + 3) * 32 + c0];
#pragma unroll
        for (int i = 0; i < 4; i++) {
            float4 xv = *(const float4*)&Xs[(e0 + i) * 68 + kk];
            acc[i][0] += xv.x * w0.x + xv.y * w1.x + xv.z * w2.x + xv.w * w3.x;
            acc[i][1] += xv.x * w0.y + xv.y * w1.y + xv.z * w2.y + xv.w * w3.y;
            acc[i][2] += xv.x * w0.z + xv.y * w1.z + xv.z * w2.z + xv.w * w3.z;
            acc[i][3] += xv.x * w0.w + xv.y * w1.w + xv.z * w2.w + xv.w * w3.w;
        }
    }
#pragma unroll
    for (int i = 0; i < 4; i++) {
        float4 o = make_float4(acc[i][0], acc[i][1], acc[i][2], acc[i][3]);
        *(float4*)(g_dense + (size_t)(n0 + e0 + i) * 32 + c0) = o;
    }
}

__global__ void msg_combo_k(const int* __restrict__ ei) {
    __shared__ float Ws[2048];
    __shared__ float Xs[128 * 68];
    __shared__ int Srcs[128];
    __shared__ int Dsts[128];
    const int tid = threadIdx.x;
    const int c = blockIdx.x;
    const int start = g_off[c];
    const int cnt = g_hist[c];
    if (cnt == 0) return;
    const float* Wp = g_W + (size_t)c * 2048;
    for (int i = tid; i < 512; i += 256)
        ((float4*)Ws)[i] = ((const float4*)Wp)[i];

    for (int base = 0; base < cnt; base += 128) {
        int nloc = min(128, cnt - base);
        __syncthreads();
        for (int j = tid; j < nloc; j += 256) {
            int e = g_sorted[start + base + j];
            Srcs[j] = ei[e];
            Dsts[j] = ei[ETOT + e];
        }
        __syncthreads();
        for (int idx = tid; idx < nloc * 16; idx += 256) {
            int j = idx >> 4, kq = idx & 15;
            ((float4*)(Xs + j * 68))[kq] = ((const float4*)(g_x + (size_t)Srcs[j] * 64))[kq];
        }
        __syncthreads();
        const int e0 = (tid >> 3) << 2;
        const int c0 = (tid & 7) << 2;
        float acc[4][4] = {};
#pragma unroll 4
        for (int kk = 0; kk < 64; kk += 4) {
            float4 w0 = *(const float4*)&Ws[(kk + 0) * 32 + c0];
            float4 w1 = *(const float4*)&Ws[(kk + 1) * 32 + c0];
            float4 w2 = *(const float4*)&Ws[(kk + 2) * 32 + c0];
            float4 w3 = *(const float4*)&Ws[(kk + 3) * 32 + c0];
#pragma unroll
            for (int i = 0; i < 4; i++) {
                float4 xv = *(const float4*)&Xs[(e0 + i) * 68 + kk];
                acc[i][0] += xv.x * w0.x + xv.y * w1.x + xv.z * w2.x + xv.w * w3.x;
                acc[i][1] += xv.x * w0.y + xv.y * w1.y + xv.z * w2.y + xv.w * w3.y;
                acc[i][2] += xv.x * w0.z + xv.y * w1.z + xv.z * w2.z + xv.w * w3.z;
                acc[i][3] += xv.x * w0.w + xv.y * w1.w + xv.z * w2.w + xv.w * w3.w;
            }
        }
#pragma unroll
        for (int i = 0; i < 4; i++) {
            int j = e0 + i;
            if (j < nloc) {
                float* dp = &g_dense[(size_t)Dsts[j] * 32 + c0];
                atomicAdd(dp + 0, acc[i][0]); atomicAdd(dp + 1, acc[i][1]);
                atomicAdd(dp + 2, acc[i][2]); atomicAdd(dp + 3, acc[i][3]);
            }
        }
    }
}

// ---------------- readout tail ----------------------------------------------
__global__ void head_k(const float* __restrict__ mW3, const float* __restrict__ mb3,
                       const float* __restrict__ mW4, const float* __restrict__ mb4,
                       const float* __restrict__ mW5, const float* __restrict__ mb5,
                       const float* __restrict__ mb2, float* __restrict__ out) {
    __shared__ float W3[128 * 32];
    __shared__ float W4[32 * 8];
    __shared__ float W5[8];
    __shared__ float B3[32], B4[8], B2[128], B5;
    const int tid = threadIdx.x;
    for (int i = tid; i < 4096; i += 256) W3[i] = mW3[i];
    if (tid < 256) W4[tid] = mW4[tid];
    if (tid < 128) B2[tid] = mb2[tid];
    if (tid < 32) B3[tid] = mb3[tid];
    if (tid < 8)  { W5[tid] = mW5[tid]; B4[tid] = mb4[tid]; }
    if (tid == 0) B5 = mb5[0];
    __syncthreads();
    const int warp = tid >> 5, lane = tid & 31;
    const int g = blockIdx.x * 8 + warp;
    const float* f2 = g_f2 + (size_t)g * 128;
    float acc = B3[lane];
#pragma unroll 4
    for (int k = 0; k < 128; k++) {
        float v = fmaxf(f2[k] + B2[k], 0.f);
        acc += v * W3[k * 32 + lane];
    }
    acc = fmaxf(acc, 0.f);
    float acc4 = (lane < 8) ? B4[lane] : 0.f;
#pragma unroll
    for (int k = 0; k < 32; k++) {
        float f3k = __shfl_sync(0xffffffffu, acc, k);
        if (lane < 8) acc4 += f3k * W4[k * 8 + lane];
    }
    acc4 = fmaxf(acc4, 0.f);
    float r = 0.f;
#pragma unroll
    for (int k = 0; k < 8; k++) {
        float f4k = __shfl_sync(0xffffffffu, acc4, k);
        r += f4k * W5[k];
    }
    if (lane == 0) out[g] = r + B5;
}

// ---------------- launch ----------------------------------------------------
extern "C" void kernel_launch(void* const* d_in, const int* in_sizes, int n_in,
                              void* d_out, int out_size) {
    (void)in_sizes; (void)n_in; (void)out_size;
    const int*   nf   = (const int*)d_in[0];
    const int*   ef   = (const int*)d_in[1];
    const int*   ei   = (const int*)d_in[2];
    const float* atom = (const float*)d_in[4];
    const float* bond = (const float*)d_in[5];
    const float* gW1  = (const float*)d_in[6];
    const float* gW2  = (const float*)d_in[7];
    const float* gW3  = (const float*)d_in[8];
    const float* root = (const float*)d_in[9];
    const float* cb   = (const float*)d_in[10];
    const float* mW1  = (const float*)d_in[11];
    const float* mb1  = (const float*)d_in[12];
    const float* mW2  = (const float*)d_in[13];
    const float* mb2  = (const float*)d_in[14];
    const float* mW3  = (const float*)d_in[15];
    const float* mb3  = (const float*)d_in[16];
    const float* mW4  = (const float*)d_in[17];
    const float* mb4  = (const float*)d_in[18];
    const float* mW5  = (const float*)d_in[19];
    const float* mb5  = (const float*)d_in[20];
    float* out = (float*)d_out;

    float *p_h1, *p_h2, *p_W, *p_dense, *p_f1, *p_f2, *p_b1;
    int* p_hist;
    cudaGetSymbolAddress((void**)&p_h1,    g_h1);
    cudaGetSymbolAddress((void**)&p_h2,    g_h2);
    cudaGetSymbolAddress((void**)&p_W,     g_W);
    cudaGetSymbolAddress((void**)&p_dense, g_dense);
    cudaGetSymbolAddress((void**)&p_f1,    g_f1);
    cudaGetSymbolAddress((void**)&p_f2,    g_f2);
    cudaGetSymbolAddress((void**)&p_b1,    g_bias1);
    cudaGetSymbolAddress((void**)&p_hist,  g_hist);

    static cudaStream_t s1 = nullptr, s2 = nullptr, s3 = nullptr;
    static cudaEvent_t evFork, evW, evF, evS;
    if (!s1) {
        cudaStreamCreateWithFlags(&s1, cudaStreamNonBlocking);
        cudaStreamCreateWithFlags(&s2, cudaStreamNonBlocking);
        cudaStreamCreateWithFlags(&s3, cudaStreamNonBlocking);
        cudaEventCreateWithFlags(&evFork, cudaEventDisableTiming);
        cudaEventCreateWithFlags(&evW, cudaEventDisableTiming);
        cudaEventCreateWithFlags(&evF, cudaEventDisableTiming);
        cudaEventCreateWithFlags(&evS, cudaEventDisableTiming);
    }

    cudaEventRecord(evFork, 0);
    cudaStreamWaitEvent(s1, evFork, 0);
    cudaStreamWaitEvent(s2, evFork, 0);
    cudaStreamWaitEvent(s3, evFork, 0);

    // s1: zero scratch + edge-weight MLP chain (E3 plain-stores into g_W)
    zero2_k<<<128, 256, 0, s1>>>((float4*)p_h2, NC * 256 / 4,
                                 (float4*)p_f2, GTOT * 128 / 4);
    gemmE1_k<<<dim3(16, 8), 256, 0, s1>>>(bond, gW1);
    gemm3_k<false, false><<<dim3(2, 8, 8), 256, 0, s1>>>(p_h1, gW2, p_h2, 256, 1024, 256, 128);
    gemm3_k<true,  true ><<<dim3(16, 8, 1), 256, 0, s1>>>(p_h2, gW3, p_W, 2048, 256, 2048, 256);
    cudaEventRecord(evW, s1);

    // s2: edge combo sort chain
    cudaMemsetAsync(p_hist, 0, NC * sizeof(int), s2);
    combo_k<<<ETOT / 256, 256, 0, s2>>>(ef);
    scan_k<<<1, 512, 0, s2>>>();
    scatter_k<<<ETOT / 256, 256, 0, s2>>>();
    cudaEventRecord(evS, s2);

    // s3: readout-bias precompute + f1 init
    cudaMemsetAsync(p_b1, 0, 256 * sizeof(float), s3);
    biasR1_k<<<160, 256, 0, s3>>>(mW1, cb);
    f1init_k<<<1024, 256, 0, s3>>>(mb1);
    cudaEventRecord(evF, s3);

    // main: node encode + root GEMM
    encode_x_k<<<NTOT / 4, 256>>>(nf, atom);
    msg_root_k<<<NTOT / 128, 256>>>(root);

    cudaStreamWaitEvent(0, evW, 0);
    cudaStreamWaitEvent(0, evS, 0);
    msg_combo_k<<<NC, 256>>>(ei);

    cudaStreamWaitEvent(0, evF, 0);
    gemm3_k<false, false><<<dim3(2, 16, 8), 256>>>(p_dense, mW1, p_f1, 256, 1280, 256, 160);
    gemm3_k<true,  false><<<dim3(1, 16, 8), 256>>>(p_f1, mW2, p_f2, 128, 256, 128, 32);
    head_k<<<GTOT / 8, 256>>>(mW3, mb3, mW4, mb4, mW5, mb5, mb2, out);
}